// round 9
// baseline (speedup 1.0000x reference)
#include <cuda_runtime.h>
#include <math.h>

#define N_NODES 50000
#define N_EDGES 800000
#define DIM 128
#define EPS_BETA 1e-6f
#define EPS_BN 1e-5f
#define CHUNK 256
#define NCHUNK ((N_NODES + CHUNK - 1) / CHUNK)   // 196

typedef unsigned long long ull;

#define FMA_F32X2(d, a, b, c) \
    asm("fma.rn.f32x2 %0, %1, %2, %3;" : "=l"(d) : "l"(a), "l"(b), "l"(c))

// ---------------- scratch (device globals; no allocation allowed) ----------
__device__ float  d_z[N_NODES * DIM];      // fc output
__device__ float  d_ssrc[N_NODES];         // z . w_src
__device__ float  d_sdst[N_NODES];         // z . w_dst
__device__ float  d_hnew[N_NODES * DIM];   // aggregated output (pre-BN)
__device__ float2 d_w2[DIM * DIM];         // duplicated weights {w,w}
__device__ int    d_deg[N_NODES];
__device__ int    d_rowstart[N_NODES + 1];
__device__ int    d_cursor[N_NODES];
__device__ int    d_src_csr[N_EDGES];
__device__ float  d_sigma_csr[N_EDGES];
__device__ int    d_chunksum[NCHUNK];
__device__ int    d_chunkoff[NCHUNK];
__device__ double d_colsum[DIM];
__device__ double d_colsq[DIM];
__device__ float  d_scale[DIM];
__device__ float  d_shift[DIM];

// ---------------- init ------------------------------------------------------
__global__ void init_kernel() {
    int i = blockIdx.x * blockDim.x + threadIdx.x;
    int stride = gridDim.x * blockDim.x;
    for (int idx = i; idx < N_NODES; idx += stride) d_deg[idx] = 0;
    if (i < DIM) { d_colsum[i] = 0.0; d_colsq[i] = 0.0; }
}

// ---------------- weight duplication: d_w2[i] = {w[i], w[i]} ----------------
__global__ void wdup_kernel(const float* __restrict__ fc_w) {
    int i = blockIdx.x * blockDim.x + threadIdx.x;   // 16384 elems
    if (i < DIM * DIM) {
        float w = __ldg(fc_w + i);
        d_w2[i] = make_float2(w, w);
    }
}

// ---------------- GEMM: z = h @ fc_w + fc_b via packed f32x2 FFMA -----------
// Block: 256 threads, 64 rows x 128 cols. Warp ty owns rows [ty*8, ty*8+8)
// as 4 row-pairs; lane tx owns cols [4tx, 4tx+4).
// hs_t is the h tile TRANSPOSED so a row-pair is one broadcast LDS.64.
__global__ void gemm_kernel(const float* __restrict__ h,
                            const float* __restrict__ fc_b,
                            const float* __restrict__ attn_w) {
    __shared__ float hs_t[DIM][64];   // [k][row], 32 KB

    const int base = blockIdx.x * 64;
    const int t  = threadIdx.x;
    const int tx = t & 31;
    const int ty = t >> 5;

    // stage h tile transposed. mapping: lanes take consecutive rows (conflict-
    // free STS); each thread loads float4 (4 k-values) of one row.
    {
        const int valid_rows = min(64, N_NODES - base);
        for (int i = t; i < 64 * (DIM / 4); i += 256) {   // 2048 float4 slots
            int row  = i & 63;
            int kvec = i >> 6;                             // 0..31
            float4 v = make_float4(0.f, 0.f, 0.f, 0.f);
            if (row < valid_rows)
                v = __ldg(reinterpret_cast<const float4*>(
                        h + (size_t)(base + row) * DIM) + kvec);
            hs_t[4 * kvec + 0][row] = v.x;
            hs_t[4 * kvec + 1][row] = v.y;
            hs_t[4 * kvec + 2][row] = v.z;
            hs_t[4 * kvec + 3][row] = v.w;
        }
    }
    __syncthreads();

    // acc2[p][c]: lo = row 2p, hi = row 2p+1, col 4tx+c
    ull acc2[4][4];
#pragma unroll
    for (int p = 0; p < 4; p++)
#pragma unroll
        for (int c = 0; c < 4; c++) acc2[p][c] = 0ull;

    const ull* w2p = reinterpret_cast<const ull*>(d_w2);

#pragma unroll 4
    for (int k = 0; k < DIM; k++) {
        ull wv[4];
#pragma unroll
        for (int c = 0; c < 4; c++)
            wv[c] = __ldg(w2p + (size_t)k * DIM + 4 * tx + c);
        ull av[4];
#pragma unroll
        for (int p = 0; p < 4; p++)
            av[p] = *reinterpret_cast<const ull*>(&hs_t[k][ty * 8 + 2 * p]);
#pragma unroll
        for (int p = 0; p < 4; p++)
#pragma unroll
            for (int c = 0; c < 4; c++)
                FMA_F32X2(acc2[p][c], av[p], wv[c], acc2[p][c]);
    }

    float4 b4   = __ldg(reinterpret_cast<const float4*>(fc_b) + tx);
    float4 wsrc = __ldg(reinterpret_cast<const float4*>(attn_w) + tx);
    float4 wdst = __ldg(reinterpret_cast<const float4*>(attn_w + DIM) + tx);

#pragma unroll
    for (int p = 0; p < 4; p++) {
#pragma unroll
        for (int half = 0; half < 2; half++) {
            int row = base + ty * 8 + 2 * p + half;
            if (row >= N_NODES) continue;
            float4 zv;
            {
                unsigned lo, hi;
                asm("mov.b64 {%0, %1}, %2;" : "=r"(lo), "=r"(hi) : "l"(acc2[p][0]));
                zv.x = __uint_as_float(half ? hi : lo) + b4.x;
                asm("mov.b64 {%0, %1}, %2;" : "=r"(lo), "=r"(hi) : "l"(acc2[p][1]));
                zv.y = __uint_as_float(half ? hi : lo) + b4.y;
                asm("mov.b64 {%0, %1}, %2;" : "=r"(lo), "=r"(hi) : "l"(acc2[p][2]));
                zv.z = __uint_as_float(half ? hi : lo) + b4.z;
                asm("mov.b64 {%0, %1}, %2;" : "=r"(lo), "=r"(hi) : "l"(acc2[p][3]));
                zv.w = __uint_as_float(half ? hi : lo) + b4.w;
            }
            reinterpret_cast<float4*>(d_z + (size_t)row * DIM)[tx] = zv;

            float ps = zv.x * wsrc.x + zv.y * wsrc.y + zv.z * wsrc.z + zv.w * wsrc.w;
            float pd = zv.x * wdst.x + zv.y * wdst.y + zv.z * wdst.z + zv.w * wdst.w;
#pragma unroll
            for (int off = 16; off > 0; off >>= 1) {
                ps += __shfl_down_sync(0xFFFFFFFFu, ps, off);
                pd += __shfl_down_sync(0xFFFFFFFFu, pd, off);
            }
            if (tx == 0) { d_ssrc[row] = ps; d_sdst[row] = pd; }
        }
    }
}

// ---------------- CSR build --------------------------------------------------
__global__ void hist_kernel(const int* __restrict__ dst) {
    int i = blockIdx.x * blockDim.x + threadIdx.x;
    if (i >= N_EDGES) return;
    atomicAdd(&d_deg[__ldg(dst + i)], 1);
}

// level 1: per-chunk sums (grid = NCHUNK, block = 256)
__global__ void chunksum_kernel() {
    __shared__ int sh[8];
    int idx = blockIdx.x * CHUNK + threadIdx.x;
    int v = (idx < N_NODES) ? d_deg[idx] : 0;
#pragma unroll
    for (int off = 16; off > 0; off >>= 1) v += __shfl_xor_sync(0xFFFFFFFFu, v, off);
    if ((threadIdx.x & 31) == 0) sh[threadIdx.x >> 5] = v;
    __syncthreads();
    if (threadIdx.x < 8) {
        int s = sh[threadIdx.x];
#pragma unroll
        for (int off = 4; off > 0; off >>= 1) s += __shfl_xor_sync(0xFFu, s, off);
        if (threadIdx.x == 0) d_chunksum[blockIdx.x] = s;
    }
}

// level 2: exclusive scan of NCHUNK (=196) chunk sums in ONE small block
__global__ void chunkscan_kernel() {
    __shared__ int sh[256];
    int t = threadIdx.x;
    int v = (t < NCHUNK) ? d_chunksum[t] : 0;
    sh[t] = v;
    __syncthreads();
#pragma unroll
    for (int off = 1; off < 256; off <<= 1) {
        int u = (t >= off) ? sh[t - off] : 0;
        __syncthreads();
        sh[t] += u;
        __syncthreads();
    }
    if (t < NCHUNK) d_chunkoff[t] = sh[t] - v;     // exclusive
    if (t == 0) d_rowstart[N_NODES] = N_EDGES;
}

// level 3: in-block exclusive scan of degrees + chunk offset -> rowstart
__global__ void rowstart_kernel() {
    __shared__ int warp_sums[8];
    int t = threadIdx.x;
    int idx = blockIdx.x * CHUNK + t;
    int v = (idx < N_NODES) ? d_deg[idx] : 0;

    int incl = v;
#pragma unroll
    for (int off = 1; off < 32; off <<= 1) {
        int u = __shfl_up_sync(0xFFFFFFFFu, incl, off);
        if ((t & 31) >= off) incl += u;
    }
    if ((t & 31) == 31) warp_sums[t >> 5] = incl;
    __syncthreads();
    if (t < 8) {
        int s = warp_sums[t];
        int si = s;
#pragma unroll
        for (int off = 1; off < 8; off <<= 1) {
            int u = __shfl_up_sync(0xFFu, si, off);
            if (t >= off) si += u;
        }
        warp_sums[t] = si - s;
    }
    __syncthreads();
    int excl = incl - v + warp_sums[t >> 5];
    if (idx < N_NODES) {
        int rs = d_chunkoff[blockIdx.x] + excl;
        d_rowstart[idx] = rs;
        d_cursor[idx]   = rs;
    }
}

__global__ void fill_kernel(const int* __restrict__ src, const int* __restrict__ dst,
                            const float* __restrict__ sigma) {
    int i = blockIdx.x * blockDim.x + threadIdx.x;
    if (i >= N_EDGES) return;
    int d = __ldg(dst + i);
    int pos = atomicAdd(&d_cursor[d], 1);
    d_src_csr[pos]   = __ldg(src + i);
    d_sigma_csr[pos] = __ldg(sigma + i);
}

// ---------------- fused per-node softmax + aggregation ----------------------
__global__ void node_kernel(const float* __restrict__ attn_b) {
    int gid  = blockIdx.x * blockDim.x + threadIdx.x;
    int node = gid >> 5;
    int lane = gid & 31;
    if (node >= N_NODES) return;

    int start = d_rowstart[node];
    int end   = d_rowstart[node + 1];
    float4 acc = make_float4(0.f, 0.f, 0.f, 0.f);
    float4* outp = reinterpret_cast<float4*>(d_hnew + (size_t)node * DIM) + lane;

    if (start == end) { *outp = acc; return; }

    const float sd = d_sdst[node];
    const float b  = __ldg(attn_b);

    float sum_ex = 0.f, sum_sg = 0.f;
    for (int j = start + lane; j < end; j += 32) {
        float a = d_ssrc[d_src_csr[j]] + sd + b;
        float e = (a > 0.f) ? a : 0.01f * a;
        sum_ex += __expf(e);
        sum_sg += d_sigma_csr[j];
    }
#pragma unroll
    for (int off = 16; off > 0; off >>= 1) {
        sum_ex += __shfl_xor_sync(0xFFFFFFFFu, sum_ex, off);
        sum_sg += __shfl_xor_sync(0xFFFFFFFFu, sum_sg, off);
    }
    const float inv = 1.0f / (sum_ex * (sum_sg + EPS_BETA));

    for (int j = start; j < end; j++) {
        int   s = d_src_csr[j];
        float a = d_ssrc[s] + sd + b;
        float e = (a > 0.f) ? a : 0.01f * a;
        float w = __expf(e) * d_sigma_csr[j];
        float4 zv = __ldg(reinterpret_cast<const float4*>(d_z + (size_t)s * DIM) + lane);
        acc.x = fmaf(w, zv.x, acc.x);
        acc.y = fmaf(w, zv.y, acc.y);
        acc.z = fmaf(w, zv.z, acc.z);
        acc.w = fmaf(w, zv.w, acc.w);
    }
    acc.x *= inv; acc.y *= inv; acc.z *= inv; acc.w *= inv;
    *outp = acc;
}

// ---------------- BN column stats -------------------------------------------
__global__ void stats_kernel() {
    int col = threadIdx.x;              // 128 threads
    double s = 0.0, sq = 0.0;
    for (int row = blockIdx.x; row < N_NODES; row += gridDim.x) {
        float v = d_hnew[(size_t)row * DIM + col];
        s  += (double)v;
        sq += (double)v * (double)v;
    }
    atomicAdd(&d_colsum[col], s);
    atomicAdd(&d_colsq[col], sq);
}

__global__ void finalize_kernel(const float* __restrict__ gamma,
                                const float* __restrict__ beta) {
    int c = threadIdx.x;
    if (c >= DIM) return;
    double mu  = d_colsum[c] / (double)N_NODES;
    double var = d_colsq[c] / (double)N_NODES - mu * mu;
    float rstd = rsqrtf((float)var + EPS_BN);
    float g = __ldg(gamma + c);
    float b = __ldg(beta + c);
    d_scale[c] = rstd * g;
    d_shift[c] = b - (float)mu * rstd * g;
}

// ---------------- normalize + ELU -------------------------------------------
__global__ void output_kernel(float* __restrict__ out) {
    int i = blockIdx.x * blockDim.x + threadIdx.x;
    if (i >= N_NODES * DIM) return;
    int c = i & (DIM - 1);
    float x = d_hnew[i] * d_scale[c] + d_shift[c];
    out[i] = (x > 0.f) ? x : expm1f(x);
}

// ---------------- launch -----------------------------------------------------
extern "C" void kernel_launch(void* const* d_in, const int* in_sizes, int n_in,
                              void* d_out, int out_size) {
    const float* h      = (const float*)d_in[0];
    const int*   src    = (const int*)  d_in[1];
    const int*   dst    = (const int*)  d_in[2];
    const float* sigma  = (const float*)d_in[3];
    const float* fc_w   = (const float*)d_in[4];
    const float* fc_b   = (const float*)d_in[5];
    const float* attn_w = (const float*)d_in[6];
    const float* attn_b = (const float*)d_in[7];
    const float* gamma  = (const float*)d_in[8];
    const float* beta   = (const float*)d_in[9];
    float* out = (float*)d_out;

    const int EB = (N_EDGES + 255) / 256;

    init_kernel<<<64, 256>>>();
    wdup_kernel<<<(DIM * DIM + 255) / 256, 256>>>(fc_w);
    gemm_kernel<<<(N_NODES + 63) / 64, 256>>>(h, fc_b, attn_w);

    hist_kernel<<<EB, 256>>>(dst);
    chunksum_kernel<<<NCHUNK, 256>>>();
    chunkscan_kernel<<<1, 256>>>();
    rowstart_kernel<<<NCHUNK, 256>>>();
    fill_kernel<<<EB, 256>>>(src, dst, sigma);

    node_kernel<<<(N_NODES + 7) / 8, 256>>>(attn_b);

    stats_kernel<<<512, 128>>>();
    finalize_kernel<<<1, 128>>>(gamma, beta);
    output_kernel<<<(N_NODES * DIM + 1023) / 1024, 1024>>>(out);
}

// round 11
// speedup vs baseline: 1.4827x; 1.4827x over previous
#include <cuda_runtime.h>
#include <cuda_bf16.h>
#include <math.h>

#define N_NODES 50000
#define N_EDGES 800000
#define DIM 128
#define EPS_BETA 1e-6f
#define EPS_BN 1e-5f
#define CHUNK 256
#define NCHUNK ((N_NODES + CHUNK - 1) / CHUNK)   // 196
#define N_TILES ((N_NODES + 127) / 128)          // 391

typedef unsigned long long ull;

// ---------------- smem layout for GEMM block --------------------------------
#define STRIDE   272                                // bytes per 128-col bf16 row (skewed)
#define OFF_BIAS 0
#define OFF_WS   512
#define OFF_WD   1024
#define OFF_A_HI 1536
#define OFF_A_LO (OFF_A_HI + 128 * STRIDE)          // 36352
#define OFF_B_HI (OFF_A_LO + 128 * STRIDE)          // 71168
#define OFF_B_LO (OFF_B_HI + 128 * STRIDE)          // 105984
#define GEMM_SMEM (OFF_B_LO + 128 * STRIDE)         // 140800
#define OFF_ZST  OFF_A_HI                           // z staging reuses A (67584 <= 69632)
#define ZSTRIDE  132                                // words per row in z staging

__device__ __forceinline__ unsigned smem_u32(const void* p) {
    unsigned a;
    asm("{ .reg .u64 t; cvta.to.shared.u64 t, %1; cvt.u32.u64 %0, t; }"
        : "=r"(a) : "l"(p));
    return a;
}

__device__ __forceinline__ void ldm_x4(unsigned addr, unsigned& r0, unsigned& r1,
                                       unsigned& r2, unsigned& r3) {
    asm volatile("ldmatrix.sync.aligned.m8n8.x4.shared.b16 {%0,%1,%2,%3}, [%4];"
                 : "=r"(r0), "=r"(r1), "=r"(r2), "=r"(r3) : "r"(addr));
}

__device__ __forceinline__ void mma16816(float* d, const unsigned* a,
                                         unsigned b0, unsigned b1) {
    asm volatile("mma.sync.aligned.m16n8k16.row.col.f32.bf16.bf16.f32 "
                 "{%0,%1,%2,%3}, {%4,%5,%6,%7}, {%8,%9}, {%0,%1,%2,%3};"
                 : "+f"(d[0]), "+f"(d[1]), "+f"(d[2]), "+f"(d[3])
                 : "r"(a[0]), "r"(a[1]), "r"(a[2]), "r"(a[3]), "r"(b0), "r"(b1));
}

// ---------------- scratch (device globals; no allocation allowed) ----------
__device__ float  d_z[N_NODES * DIM];
__device__ float  d_ssrc[N_NODES];
__device__ float  d_sdst[N_NODES];
__device__ float  d_hnew[N_NODES * DIM];
__device__ __align__(16) __nv_bfloat16 d_wimg_hi[DIM * DIM];  // [n][k] transposed weights
__device__ __align__(16) __nv_bfloat16 d_wimg_lo[DIM * DIM];
__device__ int    d_deg[N_NODES];
__device__ int    d_rowstart[N_NODES + 1];
__device__ int    d_cursor[N_NODES];
__device__ int    d_src_csr[N_EDGES];
__device__ float  d_sigma_csr[N_EDGES];
__device__ int    d_chunksum[NCHUNK];
__device__ int    d_chunkoff[NCHUNK];
__device__ double d_colsum[DIM];
__device__ double d_colsq[DIM];
__device__ float  d_scale[DIM];
__device__ float  d_shift[DIM];

// ---------------- init ------------------------------------------------------
__global__ void init_kernel() {
    int i = blockIdx.x * blockDim.x + threadIdx.x;
    int stride = gridDim.x * blockDim.x;
    for (int idx = i; idx < N_NODES; idx += stride) d_deg[idx] = 0;
    if (i < DIM) { d_colsum[i] = 0.0; d_colsq[i] = 0.0; }
}

// ---------------- weight split: wimg[n][k] = hi/lo bf16 of fc_w[k][n] -------
__global__ void wsplit_kernel(const float* __restrict__ fc_w) {
    int i = blockIdx.x * blockDim.x + threadIdx.x;
    if (i >= DIM * DIM) return;
    int k = i >> 7, n = i & 127;
    float w = __ldg(fc_w + i);                      // fc_w[k][n]
    __nv_bfloat16 hb = __float2bfloat16(w);
    float r = w - __bfloat162float(hb);
    __nv_bfloat16 lb = __float2bfloat16(r);
    d_wimg_hi[n * DIM + k] = hb;
    d_wimg_lo[n * DIM + k] = lb;
}

// ---------------- GEMM via mma.sync bf16 hi/lo split ------------------------
// Block = 256 threads (8 warps) computes one 128x128 tile of z = h@W + b,
// plus fused ssrc/sdst projections.
__global__ void __launch_bounds__(256, 1) gemm_mma_kernel(
        const float* __restrict__ h,
        const float* __restrict__ fc_b,
        const float* __restrict__ attn_w) {
    extern __shared__ char smem[];
    const unsigned sb = smem_u32(smem);
    const int t = threadIdx.x;
    const int w = t >> 5;
    const int lane = t & 31;
    const int base = blockIdx.x * 128;
    const int valid = min(128, N_NODES - base);

    // stage small vectors
    if (t < 128) {
        *(float*)(smem + OFF_BIAS + 4 * t) = __ldg(fc_b + t);
        *(float*)(smem + OFF_WS   + 4 * t) = __ldg(attn_w + t);
        *(float*)(smem + OFF_WD   + 4 * t) = __ldg(attn_w + DIM + t);
    }

    // stage B images (8 bytes = 4 bf16 per iteration)
    {
        const ull* gh = reinterpret_cast<const ull*>(d_wimg_hi);
        const ull* gl = reinterpret_cast<const ull*>(d_wimg_lo);
        for (int i = t; i < 128 * 32; i += 256) {
            int n  = i >> 5;
            int kv = i & 31;
            *(ull*)(smem + OFF_B_HI + n * STRIDE + kv * 8) = gh[n * 32 + kv];
            *(ull*)(smem + OFF_B_LO + n * STRIDE + kv * 8) = gl[n * 32 + kv];
        }
    }

    // stage A: fp32 -> bf16 hi/lo with skewed layout
#pragma unroll 4
    for (int j = 0; j < 16; j++) {
        int f4  = t + 256 * j;                      // 0..4095
        int row = f4 >> 5;
        int kv  = f4 & 31;
        float4 v = make_float4(0.f, 0.f, 0.f, 0.f);
        if (row < valid)
            v = __ldg(reinterpret_cast<const float4*>(h + (size_t)(base + row) * DIM) + kv);
        __nv_bfloat16 h0 = __float2bfloat16(v.x); float r0 = v.x - __bfloat162float(h0);
        __nv_bfloat16 h1 = __float2bfloat16(v.y); float r1 = v.y - __bfloat162float(h1);
        __nv_bfloat16 h2 = __float2bfloat16(v.z); float r2 = v.z - __bfloat162float(h2);
        __nv_bfloat16 h3 = __float2bfloat16(v.w); float r3 = v.w - __bfloat162float(h3);
        unsigned hu0 = (unsigned)__bfloat16_as_ushort(h0) |
                       ((unsigned)__bfloat16_as_ushort(h1) << 16);
        unsigned hu1 = (unsigned)__bfloat16_as_ushort(h2) |
                       ((unsigned)__bfloat16_as_ushort(h3) << 16);
        unsigned lu0 = (unsigned)__bfloat16_as_ushort(__float2bfloat16(r0)) |
                       ((unsigned)__bfloat16_as_ushort(__float2bfloat16(r1)) << 16);
        unsigned lu1 = (unsigned)__bfloat16_as_ushort(__float2bfloat16(r2)) |
                       ((unsigned)__bfloat16_as_ushort(__float2bfloat16(r3)) << 16);
        *(ull*)(smem + OFF_A_HI + row * STRIDE + kv * 8) = ((ull)hu1 << 32) | hu0;
        *(ull*)(smem + OFF_A_LO + row * STRIDE + kv * 8) = ((ull)lu1 << 32) | lu0;
    }
    __syncthreads();

    // ldmatrix per-lane address components
    const int lg = lane & 7;                        // row within 8
    const int g  = lane >> 3;                       // quadrant
    // A tiles: q0: rows m0..m0+7 k-lo | q1: +8 rows k-lo | q2: k-hi | q3: +8 k-hi
    const unsigned aRow  = (unsigned)(w * 16 + lg + ((g & 1) << 3));
    const unsigned aKoff = (unsigned)((g >> 1) << 4);
    const unsigned aHiB = sb + OFF_A_HI + aRow * STRIDE + aKoff;
    const unsigned aLoB = sb + OFF_A_LO + aRow * STRIDE + aKoff;
    // B tiles: q0: n-rows 0..7 k-lo | q1: rows 0..7 k-hi | q2: rows 8..15 k-lo | q3: rows 8..15 k-hi
    const unsigned bRow  = (unsigned)(lg + ((g >> 1) << 3));
    const unsigned bKoff = (unsigned)((g & 1) << 4);
    const unsigned bHiB = sb + OFF_B_HI + bRow * STRIDE + bKoff;
    const unsigned bLoB = sb + OFF_B_LO + bRow * STRIDE + bKoff;

    float d[16][4];
#pragma unroll
    for (int nt = 0; nt < 16; nt++)
#pragma unroll
        for (int c = 0; c < 4; c++) d[nt][c] = 0.f;

#pragma unroll
    for (int ks = 0; ks < 8; ks++) {
        unsigned ah[4], al[4];
        ldm_x4(aHiB + ks * 32, ah[0], ah[1], ah[2], ah[3]);
        ldm_x4(aLoB + ks * 32, al[0], al[1], al[2], al[3]);
#pragma unroll
        for (int p = 0; p < 8; p++) {               // pair of n-tiles
            unsigned bh[4], bl[4];
            ldm_x4(bHiB + p * (16 * STRIDE) + ks * 32, bh[0], bh[1], bh[2], bh[3]);
            ldm_x4(bLoB + p * (16 * STRIDE) + ks * 32, bl[0], bl[1], bl[2], bl[3]);
            mma16816(d[2 * p],     ah, bh[0], bh[1]);
            mma16816(d[2 * p],     ah, bl[0], bl[1]);
            mma16816(d[2 * p],     al, bh[0], bh[1]);
            mma16816(d[2 * p + 1], ah, bh[2], bh[3]);
            mma16816(d[2 * p + 1], ah, bl[2], bl[3]);
            mma16816(d[2 * p + 1], al, bh[2], bh[3]);
        }
    }
    __syncthreads();                                // A region free -> z staging

    // epilogue: bias + ssrc/sdst + z staging
    const int q  = lane >> 2;
    const int l2 = lane & 3;
    const int rA = w * 16 + q;                      // local rows rA, rA+8
    float ps0 = 0.f, pd0 = 0.f, ps1 = 0.f, pd1 = 0.f;
#pragma unroll
    for (int nt = 0; nt < 16; nt++) {
        int c0 = nt * 8 + l2 * 2;
        float2 bv = *(const float2*)(smem + OFF_BIAS + 4 * c0);
        float2 wsv = *(const float2*)(smem + OFF_WS + 4 * c0);
        float2 wdv = *(const float2*)(smem + OFF_WD + 4 * c0);
        float v0 = d[nt][0] + bv.x;
        float v1 = d[nt][1] + bv.y;
        float v2 = d[nt][2] + bv.x;
        float v3 = d[nt][3] + bv.y;
        ps0 = fmaf(v0, wsv.x, fmaf(v1, wsv.y, ps0));
        pd0 = fmaf(v0, wdv.x, fmaf(v1, wdv.y, pd0));
        ps1 = fmaf(v2, wsv.x, fmaf(v3, wsv.y, ps1));
        pd1 = fmaf(v2, wdv.x, fmaf(v3, wdv.y, pd1));
        *(float2*)(smem + OFF_ZST + (rA * ZSTRIDE + c0) * 4)       = make_float2(v0, v1);
        *(float2*)(smem + OFF_ZST + ((rA + 8) * ZSTRIDE + c0) * 4) = make_float2(v2, v3);
    }
    // reduce over the 4 lanes sharing a row
#pragma unroll
    for (int off = 1; off <= 2; off <<= 1) {
        ps0 += __shfl_xor_sync(0xFFFFFFFFu, ps0, off);
        pd0 += __shfl_xor_sync(0xFFFFFFFFu, pd0, off);
        ps1 += __shfl_xor_sync(0xFFFFFFFFu, ps1, off);
        pd1 += __shfl_xor_sync(0xFFFFFFFFu, pd1, off);
    }
    if (l2 == 0) {
        if (rA < valid)     { d_ssrc[base + rA]     = ps0; d_sdst[base + rA]     = pd0; }
        if (rA + 8 < valid) { d_ssrc[base + rA + 8] = ps1; d_sdst[base + rA + 8] = pd1; }
    }
    __syncthreads();

    // coalesced z write-out
#pragma unroll 4
    for (int j = 0; j < 16; j++) {
        int f4  = t + 256 * j;
        int row = f4 >> 5;
        int kv  = f4 & 31;
        if (row < valid) {
            float4 v = *(const float4*)(smem + OFF_ZST + (row * ZSTRIDE + kv * 4) * 4);
            *(reinterpret_cast<float4*>(d_z + (size_t)(base + row) * DIM) + kv) = v;
        }
    }
}

// ---------------- CSR build --------------------------------------------------
__global__ void hist_kernel(const int* __restrict__ dst) {
    int i = blockIdx.x * blockDim.x + threadIdx.x;
    if (i >= N_EDGES) return;
    atomicAdd(&d_deg[__ldg(dst + i)], 1);
}

__global__ void chunksum_kernel() {
    __shared__ int sh[8];
    int idx = blockIdx.x * CHUNK + threadIdx.x;
    int v = (idx < N_NODES) ? d_deg[idx] : 0;
#pragma unroll
    for (int off = 16; off > 0; off >>= 1) v += __shfl_xor_sync(0xFFFFFFFFu, v, off);
    if ((threadIdx.x & 31) == 0) sh[threadIdx.x >> 5] = v;
    __syncthreads();
    if (threadIdx.x < 8) {
        int s = sh[threadIdx.x];
#pragma unroll
        for (int off = 4; off > 0; off >>= 1) s += __shfl_xor_sync(0xFFu, s, off);
        if (threadIdx.x == 0) d_chunksum[blockIdx.x] = s;
    }
}

__global__ void chunkscan_kernel() {
    __shared__ int sh[256];
    int t = threadIdx.x;
    int v = (t < NCHUNK) ? d_chunksum[t] : 0;
    sh[t] = v;
    __syncthreads();
#pragma unroll
    for (int off = 1; off < 256; off <<= 1) {
        int u = (t >= off) ? sh[t - off] : 0;
        __syncthreads();
        sh[t] += u;
        __syncthreads();
    }
    if (t < NCHUNK) d_chunkoff[t] = sh[t] - v;
    if (t == 0) d_rowstart[N_NODES] = N_EDGES;
}

__global__ void rowstart_kernel() {
    __shared__ int warp_sums[8];
    int t = threadIdx.x;
    int idx = blockIdx.x * CHUNK + t;
    int v = (idx < N_NODES) ? d_deg[idx] : 0;

    int incl = v;
#pragma unroll
    for (int off = 1; off < 32; off <<= 1) {
        int u = __shfl_up_sync(0xFFFFFFFFu, incl, off);
        if ((t & 31) >= off) incl += u;
    }
    if ((t & 31) == 31) warp_sums[t >> 5] = incl;
    __syncthreads();
    if (t < 8) {
        int s = warp_sums[t];
        int si = s;
#pragma unroll
        for (int off = 1; off < 8; off <<= 1) {
            int u = __shfl_up_sync(0xFFu, si, off);
            if (t >= off) si += u;
        }
        warp_sums[t] = si - s;
    }
    __syncthreads();
    int excl = incl - v + warp_sums[t >> 5];
    if (idx < N_NODES) {
        int rs = d_chunkoff[blockIdx.x] + excl;
        d_rowstart[idx] = rs;
        d_cursor[idx]   = rs;
    }
}

__global__ void fill_kernel(const int* __restrict__ src, const int* __restrict__ dst,
                            const float* __restrict__ sigma) {
    int i = blockIdx.x * blockDim.x + threadIdx.x;
    if (i >= N_EDGES) return;
    int d = __ldg(dst + i);
    int pos = atomicAdd(&d_cursor[d], 1);
    d_src_csr[pos]   = __ldg(src + i);
    d_sigma_csr[pos] = __ldg(sigma + i);
}

// ---------------- fused per-node softmax + aggregation ----------------------
__global__ void node_kernel(const float* __restrict__ attn_b) {
    int gid  = blockIdx.x * blockDim.x + threadIdx.x;
    int node = gid >> 5;
    int lane = gid & 31;
    if (node >= N_NODES) return;

    int start = d_rowstart[node];
    int end   = d_rowstart[node + 1];
    float4 acc = make_float4(0.f, 0.f, 0.f, 0.f);
    float4* outp = reinterpret_cast<float4*>(d_hnew + (size_t)node * DIM) + lane;

    if (start == end) { *outp = acc; return; }

    const float sd = d_sdst[node];
    const float b  = __ldg(attn_b);

    float sum_ex = 0.f, sum_sg = 0.f;
    for (int j = start + lane; j < end; j += 32) {
        float a = d_ssrc[d_src_csr[j]] + sd + b;
        float e = (a > 0.f) ? a : 0.01f * a;
        sum_ex += __expf(e);
        sum_sg += d_sigma_csr[j];
    }
#pragma unroll
    for (int off = 16; off > 0; off >>= 1) {
        sum_ex += __shfl_xor_sync(0xFFFFFFFFu, sum_ex, off);
        sum_sg += __shfl_xor_sync(0xFFFFFFFFu, sum_sg, off);
    }
    const float inv = 1.0f / (sum_ex * (sum_sg + EPS_BETA));

    for (int j = start; j < end; j++) {
        int   s = d_src_csr[j];
        float a = d_ssrc[s] + sd + b;
        float e = (a > 0.f) ? a : 0.01f * a;
        float w = __expf(e) * d_sigma_csr[j];
        float4 zv = __ldg(reinterpret_cast<const float4*>(d_z + (size_t)s * DIM) + lane);
        acc.x = fmaf(w, zv.x, acc.x);
        acc.y = fmaf(w, zv.y, acc.y);
        acc.z = fmaf(w, zv.z, acc.z);
        acc.w = fmaf(w, zv.w, acc.w);
    }
    acc.x *= inv; acc.y *= inv; acc.z *= inv; acc.w *= inv;
    *outp = acc;
}

// ---------------- BN column stats -------------------------------------------
__global__ void stats_kernel() {
    int col = threadIdx.x;
    double s = 0.0, sq = 0.0;
    for (int row = blockIdx.x; row < N_NODES; row += gridDim.x) {
        float v = d_hnew[(size_t)row * DIM + col];
        s  += (double)v;
        sq += (double)v * (double)v;
    }
    atomicAdd(&d_colsum[col], s);
    atomicAdd(&d_colsq[col], sq);
}

__global__ void finalize_kernel(const float* __restrict__ gamma,
                                const float* __restrict__ beta) {
    int c = threadIdx.x;
    if (c >= DIM) return;
    double mu  = d_colsum[c] / (double)N_NODES;
    double var = d_colsq[c] / (double)N_NODES - mu * mu;
    float rstd = rsqrtf((float)var + EPS_BN);
    float g = __ldg(gamma + c);
    float b = __ldg(beta + c);
    d_scale[c] = rstd * g;
    d_shift[c] = b - (float)mu * rstd * g;
}

// ---------------- normalize + ELU -------------------------------------------
__global__ void output_kernel(float* __restrict__ out) {
    int i = blockIdx.x * blockDim.x + threadIdx.x;
    if (i >= N_NODES * DIM) return;
    int c = i & (DIM - 1);
    float x = d_hnew[i] * d_scale[c] + d_shift[c];
    out[i] = (x > 0.f) ? x : expm1f(x);
}

// ---------------- launch -----------------------------------------------------
extern "C" void kernel_launch(void* const* d_in, const int* in_sizes, int n_in,
                              void* d_out, int out_size) {
    const float* h      = (const float*)d_in[0];
    const int*   src    = (const int*)  d_in[1];
    const int*   dst    = (const int*)  d_in[2];
    const float* sigma  = (const float*)d_in[3];
    const float* fc_w   = (const float*)d_in[4];
    const float* fc_b   = (const float*)d_in[5];
    const float* attn_w = (const float*)d_in[6];
    const float* attn_b = (const float*)d_in[7];
    const float* gamma  = (const float*)d_in[8];
    const float* beta   = (const float*)d_in[9];
    float* out = (float*)d_out;

    const int EB = (N_EDGES + 255) / 256;

    cudaFuncSetAttribute(gemm_mma_kernel,
                         cudaFuncAttributeMaxDynamicSharedMemorySize, GEMM_SMEM);

    init_kernel<<<64, 256>>>();
    wsplit_kernel<<<(DIM * DIM + 255) / 256, 256>>>(fc_w);
    gemm_mma_kernel<<<N_TILES, 256, GEMM_SMEM>>>(h, fc_b, attn_w);

    hist_kernel<<<EB, 256>>>(dst);
    chunksum_kernel<<<NCHUNK, 256>>>();
    chunkscan_kernel<<<1, 256>>>();
    rowstart_kernel<<<NCHUNK, 256>>>();
    fill_kernel<<<EB, 256>>>(src, dst, sigma);

    node_kernel<<<(N_NODES + 7) / 8, 256>>>(attn_b);

    stats_kernel<<<512, 128>>>();
    finalize_kernel<<<1, 128>>>(gamma, beta);
    output_kernel<<<(N_NODES * DIM + 1023) / 1024, 1024>>>(out);
}

// round 12
// speedup vs baseline: 1.5682x; 1.0577x over previous
#include <cuda_runtime.h>
#include <cuda_bf16.h>
#include <math.h>

#define N_NODES 50000
#define N_EDGES 800000
#define DIM 128
#define EPS_BETA 1e-6f
#define EPS_BN 1e-5f
#define CHUNK 256
#define NCHUNK ((N_NODES + CHUNK - 1) / CHUNK)   // 196
#define N_TILES ((N_NODES + 127) / 128)          // 391

typedef unsigned long long ull;

// ---------------- smem layout for GEMM block --------------------------------
#define STRIDE   272                                // bytes per 128-col bf16 row (skewed)
#define OFF_BIAS 0
#define OFF_WS   512
#define OFF_WD   1024
#define OFF_A_HI 1536
#define OFF_A_LO (OFF_A_HI + 128 * STRIDE)          // 36352
#define OFF_B_HI (OFF_A_LO + 128 * STRIDE)          // 71168
#define OFF_B_LO (OFF_B_HI + 128 * STRIDE)          // 105984
#define GEMM_SMEM (OFF_B_LO + 128 * STRIDE)         // 140800
#define OFF_ZST  OFF_A_HI                           // z staging reuses A region
#define ZSTRIDE  132                                // words per row in z staging

__device__ __forceinline__ unsigned smem_u32(const void* p) {
    unsigned a;
    asm("{ .reg .u64 t; cvta.to.shared.u64 t, %1; cvt.u32.u64 %0, t; }"
        : "=r"(a) : "l"(p));
    return a;
}

__device__ __forceinline__ void ldm_x4(unsigned addr, unsigned& r0, unsigned& r1,
                                       unsigned& r2, unsigned& r3) {
    asm volatile("ldmatrix.sync.aligned.m8n8.x4.shared.b16 {%0,%1,%2,%3}, [%4];"
                 : "=r"(r0), "=r"(r1), "=r"(r2), "=r"(r3) : "r"(addr));
}

// NOTE: not volatile — let ptxas schedule MMAs to hide HMMA latency.
__device__ __forceinline__ void mma16816(float* d, const unsigned* a,
                                         unsigned b0, unsigned b1) {
    asm("mma.sync.aligned.m16n8k16.row.col.f32.bf16.bf16.f32 "
        "{%0,%1,%2,%3}, {%4,%5,%6,%7}, {%8,%9}, {%0,%1,%2,%3};"
        : "+f"(d[0]), "+f"(d[1]), "+f"(d[2]), "+f"(d[3])
        : "r"(a[0]), "r"(a[1]), "r"(a[2]), "r"(a[3]), "r"(b0), "r"(b1));
}

// ---------------- scratch (device globals; no allocation allowed) ----------
__device__ float  d_z[N_NODES * DIM];
__device__ float  d_ssrc[N_NODES];
__device__ float  d_sdst[N_NODES];
__device__ float  d_hnew[N_NODES * DIM];
__device__ __align__(16) __nv_bfloat16 d_wimg_hi[DIM * DIM];  // [n][k] transposed weights
__device__ __align__(16) __nv_bfloat16 d_wimg_lo[DIM * DIM];
__device__ int    d_deg[N_NODES];
__device__ int    d_rowstart[N_NODES + 1];
__device__ int    d_cursor[N_NODES];
__device__ int2   d_ecsr[N_EDGES];                 // {src, sigma-as-int}
__device__ int    d_chunksum[NCHUNK];
__device__ int    d_chunkoff[NCHUNK];
__device__ double d_colsum[DIM];
__device__ double d_colsq[DIM];
__device__ float  d_scale[DIM];
__device__ float  d_shift[DIM];

// ---------------- init ------------------------------------------------------
__global__ void init_kernel() {
    int i = blockIdx.x * blockDim.x + threadIdx.x;
    int stride = gridDim.x * blockDim.x;
    for (int idx = i; idx < N_NODES; idx += stride) d_deg[idx] = 0;
    if (i < DIM) { d_colsum[i] = 0.0; d_colsq[i] = 0.0; }
}

// ---------------- weight split: wimg[n][k] = hi/lo bf16 of fc_w[k][n] -------
__global__ void wsplit_kernel(const float* __restrict__ fc_w) {
    int i = blockIdx.x * blockDim.x + threadIdx.x;
    if (i >= DIM * DIM) return;
    int k = i >> 7, n = i & 127;
    float w = __ldg(fc_w + i);                      // fc_w[k][n]
    __nv_bfloat16 hb = __float2bfloat16(w);
    float r = w - __bfloat162float(hb);
    __nv_bfloat16 lb = __float2bfloat16(r);
    d_wimg_hi[n * DIM + k] = hb;
    d_wimg_lo[n * DIM + k] = lb;
}

// ---------------- GEMM via mma.sync bf16 hi/lo split ------------------------
__global__ void __launch_bounds__(256, 1) gemm_mma_kernel(
        const float* __restrict__ h,
        const float* __restrict__ fc_b,
        const float* __restrict__ attn_w) {
    extern __shared__ char smem[];
    const unsigned sb = smem_u32(smem);
    const int t = threadIdx.x;
    const int w = t >> 5;
    const int lane = t & 31;
    const int base = blockIdx.x * 128;
    const int valid = min(128, N_NODES - base);

    if (t < 128) {
        *(float*)(smem + OFF_BIAS + 4 * t) = __ldg(fc_b + t);
        *(float*)(smem + OFF_WS   + 4 * t) = __ldg(attn_w + t);
        *(float*)(smem + OFF_WD   + 4 * t) = __ldg(attn_w + DIM + t);
    }

    {
        const ull* gh = reinterpret_cast<const ull*>(d_wimg_hi);
        const ull* gl = reinterpret_cast<const ull*>(d_wimg_lo);
        for (int i = t; i < 128 * 32; i += 256) {
            int n  = i >> 5;
            int kv = i & 31;
            *(ull*)(smem + OFF_B_HI + n * STRIDE + kv * 8) = gh[n * 32 + kv];
            *(ull*)(smem + OFF_B_LO + n * STRIDE + kv * 8) = gl[n * 32 + kv];
        }
    }

#pragma unroll 4
    for (int j = 0; j < 16; j++) {
        int f4  = t + 256 * j;
        int row = f4 >> 5;
        int kv  = f4 & 31;
        float4 v = make_float4(0.f, 0.f, 0.f, 0.f);
        if (row < valid)
            v = __ldg(reinterpret_cast<const float4*>(h + (size_t)(base + row) * DIM) + kv);
        __nv_bfloat16 h0 = __float2bfloat16(v.x); float r0 = v.x - __bfloat162float(h0);
        __nv_bfloat16 h1 = __float2bfloat16(v.y); float r1 = v.y - __bfloat162float(h1);
        __nv_bfloat16 h2 = __float2bfloat16(v.z); float r2 = v.z - __bfloat162float(h2);
        __nv_bfloat16 h3 = __float2bfloat16(v.w); float r3 = v.w - __bfloat162float(h3);
        unsigned hu0 = (unsigned)__bfloat16_as_ushort(h0) |
                       ((unsigned)__bfloat16_as_ushort(h1) << 16);
        unsigned hu1 = (unsigned)__bfloat16_as_ushort(h2) |
                       ((unsigned)__bfloat16_as_ushort(h3) << 16);
        unsigned lu0 = (unsigned)__bfloat16_as_ushort(__float2bfloat16(r0)) |
                       ((unsigned)__bfloat16_as_ushort(__float2bfloat16(r1)) << 16);
        unsigned lu1 = (unsigned)__bfloat16_as_ushort(__float2bfloat16(r2)) |
                       ((unsigned)__bfloat16_as_ushort(__float2bfloat16(r3)) << 16);
        *(ull*)(smem + OFF_A_HI + row * STRIDE + kv * 8) = ((ull)hu1 << 32) | hu0;
        *(ull*)(smem + OFF_A_LO + row * STRIDE + kv * 8) = ((ull)lu1 << 32) | lu0;
    }
    __syncthreads();

    const int lg = lane & 7;
    const int g  = lane >> 3;
    const unsigned aRow  = (unsigned)(w * 16 + lg + ((g & 1) << 3));
    const unsigned aKoff = (unsigned)((g >> 1) << 4);
    const unsigned aHiB = sb + OFF_A_HI + aRow * STRIDE + aKoff;
    const unsigned aLoB = sb + OFF_A_LO + aRow * STRIDE + aKoff;
    const unsigned bRow  = (unsigned)(lg + ((g >> 1) << 3));
    const unsigned bKoff = (unsigned)((g & 1) << 4);
    const unsigned bHiB = sb + OFF_B_HI + bRow * STRIDE + bKoff;
    const unsigned bLoB = sb + OFF_B_LO + bRow * STRIDE + bKoff;

    float d[16][4];
#pragma unroll
    for (int nt = 0; nt < 16; nt++)
#pragma unroll
        for (int c = 0; c < 4; c++) d[nt][c] = 0.f;

#pragma unroll
    for (int ks = 0; ks < 8; ks++) {
        unsigned ah[4], al[4];
        ldm_x4(aHiB + ks * 32, ah[0], ah[1], ah[2], ah[3]);
        ldm_x4(aLoB + ks * 32, al[0], al[1], al[2], al[3]);
#pragma unroll
        for (int p = 0; p < 8; p++) {
            unsigned bh[4], bl[4];
            ldm_x4(bHiB + p * (16 * STRIDE) + ks * 32, bh[0], bh[1], bh[2], bh[3]);
            ldm_x4(bLoB + p * (16 * STRIDE) + ks * 32, bl[0], bl[1], bl[2], bl[3]);
            // interleaved: consecutive MMAs hit different accumulators
            mma16816(d[2 * p],     ah, bh[0], bh[1]);
            mma16816(d[2 * p + 1], ah, bh[2], bh[3]);
            mma16816(d[2 * p],     ah, bl[0], bl[1]);
            mma16816(d[2 * p + 1], ah, bl[2], bl[3]);
            mma16816(d[2 * p],     al, bh[0], bh[1]);
            mma16816(d[2 * p + 1], al, bh[2], bh[3]);
        }
    }
    __syncthreads();                                // A region free -> z staging

    const int q  = lane >> 2;
    const int l2 = lane & 3;
    const int rA = w * 16 + q;
    float ps0 = 0.f, pd0 = 0.f, ps1 = 0.f, pd1 = 0.f;
#pragma unroll
    for (int nt = 0; nt < 16; nt++) {
        int c0 = nt * 8 + l2 * 2;
        float2 bv  = *(const float2*)(smem + OFF_BIAS + 4 * c0);
        float2 wsv = *(const float2*)(smem + OFF_WS + 4 * c0);
        float2 wdv = *(const float2*)(smem + OFF_WD + 4 * c0);
        float v0 = d[nt][0] + bv.x;
        float v1 = d[nt][1] + bv.y;
        float v2 = d[nt][2] + bv.x;
        float v3 = d[nt][3] + bv.y;
        ps0 = fmaf(v0, wsv.x, fmaf(v1, wsv.y, ps0));
        pd0 = fmaf(v0, wdv.x, fmaf(v1, wdv.y, pd0));
        ps1 = fmaf(v2, wsv.x, fmaf(v3, wsv.y, ps1));
        pd1 = fmaf(v2, wdv.x, fmaf(v3, wdv.y, pd1));
        *(float2*)(smem + OFF_ZST + (rA * ZSTRIDE + c0) * 4)       = make_float2(v0, v1);
        *(float2*)(smem + OFF_ZST + ((rA + 8) * ZSTRIDE + c0) * 4) = make_float2(v2, v3);
    }
#pragma unroll
    for (int off = 1; off <= 2; off <<= 1) {
        ps0 += __shfl_xor_sync(0xFFFFFFFFu, ps0, off);
        pd0 += __shfl_xor_sync(0xFFFFFFFFu, pd0, off);
        ps1 += __shfl_xor_sync(0xFFFFFFFFu, ps1, off);
        pd1 += __shfl_xor_sync(0xFFFFFFFFu, pd1, off);
    }
    if (l2 == 0) {
        if (rA < valid)     { d_ssrc[base + rA]     = ps0; d_sdst[base + rA]     = pd0; }
        if (rA + 8 < valid) { d_ssrc[base + rA + 8] = ps1; d_sdst[base + rA + 8] = pd1; }
    }
    __syncthreads();

#pragma unroll 4
    for (int j = 0; j < 16; j++) {
        int f4  = t + 256 * j;
        int row = f4 >> 5;
        int kv  = f4 & 31;
        if (row < valid) {
            float4 v = *(const float4*)(smem + OFF_ZST + (row * ZSTRIDE + kv * 4) * 4);
            *(reinterpret_cast<float4*>(d_z + (size_t)(base + row) * DIM) + kv) = v;
        }
    }
}

// ---------------- CSR build --------------------------------------------------
__global__ void hist_kernel(const int* __restrict__ dst) {
    int i = blockIdx.x * blockDim.x + threadIdx.x;
    if (i >= N_EDGES) return;
    atomicAdd(&d_deg[__ldg(dst + i)], 1);
}

__global__ void chunksum_kernel() {
    __shared__ int sh[8];
    int idx = blockIdx.x * CHUNK + threadIdx.x;
    int v = (idx < N_NODES) ? d_deg[idx] : 0;
#pragma unroll
    for (int off = 16; off > 0; off >>= 1) v += __shfl_xor_sync(0xFFFFFFFFu, v, off);
    if ((threadIdx.x & 31) == 0) sh[threadIdx.x >> 5] = v;
    __syncthreads();
    if (threadIdx.x < 8) {
        int s = sh[threadIdx.x];
#pragma unroll
        for (int off = 4; off > 0; off >>= 1) s += __shfl_xor_sync(0xFFu, s, off);
        if (threadIdx.x == 0) d_chunksum[blockIdx.x] = s;
    }
}

__global__ void chunkscan_kernel() {
    __shared__ int sh[256];
    int t = threadIdx.x;
    int v = (t < NCHUNK) ? d_chunksum[t] : 0;
    sh[t] = v;
    __syncthreads();
#pragma unroll
    for (int off = 1; off < 256; off <<= 1) {
        int u = (t >= off) ? sh[t - off] : 0;
        __syncthreads();
        sh[t] += u;
        __syncthreads();
    }
    if (t < NCHUNK) d_chunkoff[t] = sh[t] - v;
    if (t == 0) d_rowstart[N_NODES] = N_EDGES;
}

__global__ void rowstart_kernel() {
    __shared__ int warp_sums[8];
    int t = threadIdx.x;
    int idx = blockIdx.x * CHUNK + t;
    int v = (idx < N_NODES) ? d_deg[idx] : 0;

    int incl = v;
#pragma unroll
    for (int off = 1; off < 32; off <<= 1) {
        int u = __shfl_up_sync(0xFFFFFFFFu, incl, off);
        if ((t & 31) >= off) incl += u;
    }
    if ((t & 31) == 31) warp_sums[t >> 5] = incl;
    __syncthreads();
    if (t < 8) {
        int s = warp_sums[t];
        int si = s;
#pragma unroll
        for (int off = 1; off < 8; off <<= 1) {
            int u = __shfl_up_sync(0xFFu, si, off);
            if (t >= off) si += u;
        }
        warp_sums[t] = si - s;
    }
    __syncthreads();
    int excl = incl - v + warp_sums[t >> 5];
    if (idx < N_NODES) {
        int rs = d_chunkoff[blockIdx.x] + excl;
        d_rowstart[idx] = rs;
        d_cursor[idx]   = rs;
    }
}

__global__ void fill_kernel(const int* __restrict__ src, const int* __restrict__ dst,
                            const float* __restrict__ sigma) {
    int i = blockIdx.x * blockDim.x + threadIdx.x;
    if (i >= N_EDGES) return;
    int d = __ldg(dst + i);
    int pos = atomicAdd(&d_cursor[d], 1);
    d_ecsr[pos] = make_int2(__ldg(src + i), __float_as_int(__ldg(sigma + i)));
}

// ---------------- fused per-node softmax + aggregation ----------------------
__global__ void node_kernel(const float* __restrict__ attn_b) {
    int gid  = blockIdx.x * blockDim.x + threadIdx.x;
    int node = gid >> 5;
    int lane = gid & 31;
    if (node >= N_NODES) return;

    int start = d_rowstart[node];
    int end   = d_rowstart[node + 1];
    float4 acc = make_float4(0.f, 0.f, 0.f, 0.f);
    float4* outp = reinterpret_cast<float4*>(d_hnew + (size_t)node * DIM) + lane;

    if (start == end) { *outp = acc; return; }

    const float sd = d_sdst[node];
    const float b  = __ldg(attn_b);

    float sum_ex = 0.f, sum_sg = 0.f;
    for (int j = start + lane; j < end; j += 32) {
        int2 pr = d_ecsr[j];
        float a = d_ssrc[pr.x] + sd + b;
        float e = (a > 0.f) ? a : 0.01f * a;
        sum_ex += __expf(e);
        sum_sg += __int_as_float(pr.y);
    }
#pragma unroll
    for (int off = 16; off > 0; off >>= 1) {
        sum_ex += __shfl_xor_sync(0xFFFFFFFFu, sum_ex, off);
        sum_sg += __shfl_xor_sync(0xFFFFFFFFu, sum_sg, off);
    }
    const float inv = 1.0f / (sum_ex * (sum_sg + EPS_BETA));

    for (int j = start; j < end; j++) {
        int2  pr = d_ecsr[j];                      // uniform -> broadcast
        float a = d_ssrc[pr.x] + sd + b;
        float e = (a > 0.f) ? a : 0.01f * a;
        float w = __expf(e) * __int_as_float(pr.y);
        float4 zv = __ldg(reinterpret_cast<const float4*>(d_z + (size_t)pr.x * DIM) + lane);
        acc.x = fmaf(w, zv.x, acc.x);
        acc.y = fmaf(w, zv.y, acc.y);
        acc.z = fmaf(w, zv.z, acc.z);
        acc.w = fmaf(w, zv.w, acc.w);
    }
    acc.x *= inv; acc.y *= inv; acc.z *= inv; acc.w *= inv;
    *outp = acc;
}

// ---------------- BN column stats -------------------------------------------
__global__ void stats_kernel() {
    int col = threadIdx.x;
    double s = 0.0, sq = 0.0;
    for (int row = blockIdx.x; row < N_NODES; row += gridDim.x) {
        float v = d_hnew[(size_t)row * DIM + col];
        s  += (double)v;
        sq += (double)v * (double)v;
    }
    atomicAdd(&d_colsum[col], s);
    atomicAdd(&d_colsq[col], sq);
}

__global__ void finalize_kernel(const float* __restrict__ gamma,
                                const float* __restrict__ beta) {
    int c = threadIdx.x;
    if (c >= DIM) return;
    double mu  = d_colsum[c] / (double)N_NODES;
    double var = d_colsq[c] / (double)N_NODES - mu * mu;
    float rstd = rsqrtf((float)var + EPS_BN);
    float g = __ldg(gamma + c);
    float b = __ldg(beta + c);
    d_scale[c] = rstd * g;
    d_shift[c] = b - (float)mu * rstd * g;
}

// ---------------- normalize + ELU -------------------------------------------
__global__ void output_kernel(float* __restrict__ out) {
    int i = blockIdx.x * blockDim.x + threadIdx.x;
    if (i >= N_NODES * DIM) return;
    int c = i & (DIM - 1);
    float x = d_hnew[i] * d_scale[c] + d_shift[c];
    out[i] = (x > 0.f) ? x : expm1f(x);
}

// ---------------- launch -----------------------------------------------------
extern "C" void kernel_launch(void* const* d_in, const int* in_sizes, int n_in,
                              void* d_out, int out_size) {
    const float* h      = (const float*)d_in[0];
    const int*   src    = (const int*)  d_in[1];
    const int*   dst    = (const int*)  d_in[2];
    const float* sigma  = (const float*)d_in[3];
    const float* fc_w   = (const float*)d_in[4];
    const float* fc_b   = (const float*)d_in[5];
    const float* attn_w = (const float*)d_in[6];
    const float* attn_b = (const float*)d_in[7];
    const float* gamma  = (const float*)d_in[8];
    const float* beta   = (const float*)d_in[9];
    float* out = (float*)d_out;

    const int EB = (N_EDGES + 255) / 256;

    // one-time resources (host-side setup only; per-call work is identical)
    static cudaStream_t s_side = nullptr;
    static cudaEvent_t ev_fork = nullptr, ev_join = nullptr;
    if (s_side == nullptr) {
        cudaStreamCreateWithFlags(&s_side, cudaStreamNonBlocking);
        cudaEventCreateWithFlags(&ev_fork, cudaEventDisableTiming);
        cudaEventCreateWithFlags(&ev_join, cudaEventDisableTiming);
        cudaFuncSetAttribute(gemm_mma_kernel,
                             cudaFuncAttributeMaxDynamicSharedMemorySize, GEMM_SMEM);
    }

    // main stream: init, then fork CSR build to side stream while GEMM runs
    init_kernel<<<64, 256>>>();
    cudaEventRecord(ev_fork, 0);
    cudaStreamWaitEvent(s_side, ev_fork, 0);

    // side stream: CSR build (independent of GEMM)
    hist_kernel<<<EB, 256, 0, s_side>>>(dst);
    chunksum_kernel<<<NCHUNK, 256, 0, s_side>>>();
    chunkscan_kernel<<<1, 256, 0, s_side>>>();
    rowstart_kernel<<<NCHUNK, 256, 0, s_side>>>();
    fill_kernel<<<EB, 256, 0, s_side>>>(src, dst, sigma);
    cudaEventRecord(ev_join, s_side);

    // main stream: weight split + GEMM (tensor-bound; overlaps CSR)
    wsplit_kernel<<<(DIM * DIM + 255) / 256, 256>>>(fc_w);
    gemm_mma_kernel<<<N_TILES, 256, GEMM_SMEM>>>(h, fc_b, attn_w);

    // join, then the dependent tail
    cudaStreamWaitEvent(0, ev_join, 0);
    node_kernel<<<(N_NODES + 7) / 8, 256>>>(attn_b);

    stats_kernel<<<512, 128>>>();
    finalize_kernel<<<1, 128>>>(gamma, beta);
    output_kernel<<<(N_NODES * DIM + 1023) / 1024, 1024>>>(out);
}

// round 13
// speedup vs baseline: 2.0491x; 1.3066x over previous
#include <cuda_runtime.h>
#include <cuda_bf16.h>
#include <cuda_fp16.h>
#include <math.h>

#define N_NODES 50000
#define N_EDGES 800000
#define DIM 128
#define EPS_BETA 1e-6f
#define EPS_BN 1e-5f
#define CHUNK 256
#define NCHUNK ((N_NODES + CHUNK - 1) / CHUNK)   // 196
#define N_TILES ((N_NODES + 127) / 128)          // 391

typedef unsigned long long ull;

// ---------------- smem layout for GEMM block --------------------------------
#define STRIDE   272                                // bytes per 128-col bf16 row (skewed)
#define OFF_BIAS 0
#define OFF_WS   512
#define OFF_WD   1024
#define OFF_A_HI 1536
#define OFF_A_LO (OFF_A_HI + 128 * STRIDE)          // 36352
#define OFF_B_HI (OFF_A_LO + 128 * STRIDE)          // 71168
#define OFF_B_LO (OFF_B_HI + 128 * STRIDE)          // 105984
#define GEMM_SMEM (OFF_B_LO + 128 * STRIDE)         // 140800
#define OFF_ZST  OFF_A_HI                           // z staging reuses A region
#define ZSTRIDE  132                                // words per row in z staging

__device__ __forceinline__ unsigned smem_u32(const void* p) {
    unsigned a;
    asm("{ .reg .u64 t; cvta.to.shared.u64 t, %1; cvt.u32.u64 %0, t; }"
        : "=r"(a) : "l"(p));
    return a;
}

__device__ __forceinline__ void ldm_x4(unsigned addr, unsigned& r0, unsigned& r1,
                                       unsigned& r2, unsigned& r3) {
    asm volatile("ldmatrix.sync.aligned.m8n8.x4.shared.b16 {%0,%1,%2,%3}, [%4];"
                 : "=r"(r0), "=r"(r1), "=r"(r2), "=r"(r3) : "r"(addr));
}

__device__ __forceinline__ void mma16816(float* d, const unsigned* a,
                                         unsigned b0, unsigned b1) {
    asm("mma.sync.aligned.m16n8k16.row.col.f32.bf16.bf16.f32 "
        "{%0,%1,%2,%3}, {%4,%5,%6,%7}, {%8,%9}, {%0,%1,%2,%3};"
        : "+f"(d[0]), "+f"(d[1]), "+f"(d[2]), "+f"(d[3])
        : "r"(a[0]), "r"(a[1]), "r"(a[2]), "r"(a[3]), "r"(b0), "r"(b1));
}

// ---------------- scratch (device globals; no allocation allowed) ----------
__device__ uint2  d_zh[N_NODES * 32];              // z as fp16 (4 cols per uint2)
__device__ float  d_ssrc[N_NODES];
__device__ float  d_sdst[N_NODES];
__device__ float  d_hnew[N_NODES * DIM];
__device__ __align__(16) __nv_bfloat16 d_wimg_hi[DIM * DIM];  // [n][k] transposed weights
__device__ __align__(16) __nv_bfloat16 d_wimg_lo[DIM * DIM];
__device__ int    d_deg[N_NODES];
__device__ int    d_rowstart[N_NODES + 1];
__device__ int    d_cursor[N_NODES];
__device__ int2   d_ecsr[N_EDGES];                 // {src, sigma-as-int}
__device__ int    d_chunksum[NCHUNK];
__device__ int    d_chunkoff[NCHUNK];
__device__ float  d_colsum_f[DIM];
__device__ float  d_colsq_f[DIM];
__device__ float  d_scale[DIM];
__device__ float  d_shift[DIM];

// ---------------- init ------------------------------------------------------
__global__ void init_kernel() {
    int i = blockIdx.x * blockDim.x + threadIdx.x;
    int stride = gridDim.x * blockDim.x;
    for (int idx = i; idx < N_NODES; idx += stride) d_deg[idx] = 0;
    if (i < DIM) { d_colsum_f[i] = 0.f; d_colsq_f[i] = 0.f; }
}

// ---------------- weight split: wimg[n][k] = hi/lo bf16 of fc_w[k][n] -------
__global__ void wsplit_kernel(const float* __restrict__ fc_w) {
    int i = blockIdx.x * blockDim.x + threadIdx.x;
    if (i >= DIM * DIM) return;
    int k = i >> 7, n = i & 127;
    float w = __ldg(fc_w + i);                      // fc_w[k][n]
    __nv_bfloat16 hb = __float2bfloat16(w);
    float r = w - __bfloat162float(hb);
    __nv_bfloat16 lb = __float2bfloat16(r);
    d_wimg_hi[n * DIM + k] = hb;
    d_wimg_lo[n * DIM + k] = lb;
}

// ---------------- GEMM via mma.sync bf16 hi/lo split, 4Mx2N warp tiling -----
__global__ void __launch_bounds__(256, 1) gemm_mma_kernel(
        const float* __restrict__ h,
        const float* __restrict__ fc_b,
        const float* __restrict__ attn_w) {
    extern __shared__ char smem[];
    const unsigned sb = smem_u32(smem);
    const int t = threadIdx.x;
    const int w = t >> 5;
    const int lane = t & 31;
    const int base = blockIdx.x * 128;
    const int valid = min(128, N_NODES - base);

    if (t < 128) {
        *(float*)(smem + OFF_BIAS + 4 * t) = __ldg(fc_b + t);
        *(float*)(smem + OFF_WS   + 4 * t) = __ldg(attn_w + t);
        *(float*)(smem + OFF_WD   + 4 * t) = __ldg(attn_w + DIM + t);
    }

    {
        const ull* gh = reinterpret_cast<const ull*>(d_wimg_hi);
        const ull* gl = reinterpret_cast<const ull*>(d_wimg_lo);
        for (int i = t; i < 128 * 32; i += 256) {
            int n  = i >> 5;
            int kv = i & 31;
            *(ull*)(smem + OFF_B_HI + n * STRIDE + kv * 8) = gh[n * 32 + kv];
            *(ull*)(smem + OFF_B_LO + n * STRIDE + kv * 8) = gl[n * 32 + kv];
        }
    }

#pragma unroll 4
    for (int j = 0; j < 16; j++) {
        int f4  = t + 256 * j;
        int row = f4 >> 5;
        int kv  = f4 & 31;
        float4 v = make_float4(0.f, 0.f, 0.f, 0.f);
        if (row < valid)
            v = __ldg(reinterpret_cast<const float4*>(h + (size_t)(base + row) * DIM) + kv);
        __nv_bfloat16 h0 = __float2bfloat16(v.x); float r0 = v.x - __bfloat162float(h0);
        __nv_bfloat16 h1 = __float2bfloat16(v.y); float r1 = v.y - __bfloat162float(h1);
        __nv_bfloat16 h2 = __float2bfloat16(v.z); float r2 = v.z - __bfloat162float(h2);
        __nv_bfloat16 h3 = __float2bfloat16(v.w); float r3 = v.w - __bfloat162float(h3);
        unsigned hu0 = (unsigned)__bfloat16_as_ushort(h0) |
                       ((unsigned)__bfloat16_as_ushort(h1) << 16);
        unsigned hu1 = (unsigned)__bfloat16_as_ushort(h2) |
                       ((unsigned)__bfloat16_as_ushort(h3) << 16);
        unsigned lu0 = (unsigned)__bfloat16_as_ushort(__float2bfloat16(r0)) |
                       ((unsigned)__bfloat16_as_ushort(__float2bfloat16(r1)) << 16);
        unsigned lu1 = (unsigned)__bfloat16_as_ushort(__float2bfloat16(r2)) |
                       ((unsigned)__bfloat16_as_ushort(__float2bfloat16(r3)) << 16);
        *(ull*)(smem + OFF_A_HI + row * STRIDE + kv * 8) = ((ull)hu1 << 32) | hu0;
        *(ull*)(smem + OFF_A_LO + row * STRIDE + kv * 8) = ((ull)lu1 << 32) | lu0;
    }
    __syncthreads();

    // 4Mx2N warp tiling: warp (wm, wn) computes rows [wm*32, +32) x cols [wn*64, +64)
    const int wm = w & 3;
    const int wn = w >> 2;
    const int lg = lane & 7;
    const int g  = lane >> 3;
    const unsigned aKoff = (unsigned)((g >> 1) << 4);
    const unsigned aRow0 = (unsigned)(wm * 32 + lg + ((g & 1) << 3));
    const unsigned aHi0 = sb + OFF_A_HI + aRow0 * STRIDE + aKoff;
    const unsigned aLo0 = sb + OFF_A_LO + aRow0 * STRIDE + aKoff;
    const unsigned bRow  = (unsigned)(wn * 64 + lg + ((g >> 1) << 3));
    const unsigned bKoff = (unsigned)((g & 1) << 4);
    const unsigned bHiB = sb + OFF_B_HI + bRow * STRIDE + bKoff;
    const unsigned bLoB = sb + OFF_B_LO + bRow * STRIDE + bKoff;

    float d[2][8][4];
#pragma unroll
    for (int mt = 0; mt < 2; mt++)
#pragma unroll
        for (int nt = 0; nt < 8; nt++)
#pragma unroll
            for (int c = 0; c < 4; c++) d[mt][nt][c] = 0.f;

#pragma unroll
    for (int ks = 0; ks < 8; ks++) {
        unsigned ah0[4], al0[4], ah1[4], al1[4];
        ldm_x4(aHi0 + ks * 32,               ah0[0], ah0[1], ah0[2], ah0[3]);
        ldm_x4(aHi0 + 16 * STRIDE + ks * 32, ah1[0], ah1[1], ah1[2], ah1[3]);
        ldm_x4(aLo0 + ks * 32,               al0[0], al0[1], al0[2], al0[3]);
        ldm_x4(aLo0 + 16 * STRIDE + ks * 32, al1[0], al1[1], al1[2], al1[3]);
#pragma unroll
        for (int p = 0; p < 4; p++) {
            unsigned bh[4], bl[4];
            ldm_x4(bHiB + p * (16 * STRIDE) + ks * 32, bh[0], bh[1], bh[2], bh[3]);
            ldm_x4(bLoB + p * (16 * STRIDE) + ks * 32, bl[0], bl[1], bl[2], bl[3]);
            // 4 independent accumulator chains of length 3, distance 4
            mma16816(d[0][2 * p],     ah0, bh[0], bh[1]);
            mma16816(d[1][2 * p],     ah1, bh[0], bh[1]);
            mma16816(d[0][2 * p + 1], ah0, bh[2], bh[3]);
            mma16816(d[1][2 * p + 1], ah1, bh[2], bh[3]);
            mma16816(d[0][2 * p],     ah0, bl[0], bl[1]);
            mma16816(d[1][2 * p],     ah1, bl[0], bl[1]);
            mma16816(d[0][2 * p + 1], ah0, bl[2], bl[3]);
            mma16816(d[1][2 * p + 1], ah1, bl[2], bl[3]);
            mma16816(d[0][2 * p],     al0, bh[0], bh[1]);
            mma16816(d[1][2 * p],     al1, bh[0], bh[1]);
            mma16816(d[0][2 * p + 1], al0, bh[2], bh[3]);
            mma16816(d[1][2 * p + 1], al1, bh[2], bh[3]);
        }
    }
    __syncthreads();                                // A region free -> z staging

    // stage z (+bias) into smem
    const int q  = lane >> 2;
    const int l2 = lane & 3;
#pragma unroll
    for (int mt = 0; mt < 2; mt++) {
        int r0 = wm * 32 + mt * 16 + q;
#pragma unroll
        for (int nt = 0; nt < 8; nt++) {
            int c0 = wn * 64 + nt * 8 + l2 * 2;
            float2 bv = *(const float2*)(smem + OFF_BIAS + 4 * c0);
            float* dd = d[mt][nt];
            *(float2*)(smem + OFF_ZST + (r0 * ZSTRIDE + c0) * 4) =
                make_float2(dd[0] + bv.x, dd[1] + bv.y);
            *(float2*)(smem + OFF_ZST + ((r0 + 8) * ZSTRIDE + c0) * 4) =
                make_float2(dd[2] + bv.x, dd[3] + bv.y);
        }
    }
    __syncthreads();

    // write-out: fp16 z + fused ssrc/sdst per-row warp reductions
    const float4 ws4 = *(const float4*)(smem + OFF_WS + 16 * lane);
    const float4 wd4 = *(const float4*)(smem + OFF_WD + 16 * lane);
#pragma unroll 2
    for (int j = 0; j < 16; j++) {
        int row = w + 8 * j;
        float4 v = *(const float4*)(smem + OFF_ZST + (row * ZSTRIDE + 4 * lane) * 4);
        float ps = v.x * ws4.x + v.y * ws4.y + v.z * ws4.z + v.w * ws4.w;
        float pd = v.x * wd4.x + v.y * wd4.y + v.z * wd4.z + v.w * wd4.w;
#pragma unroll
        for (int off = 16; off > 0; off >>= 1) {
            ps += __shfl_down_sync(0xFFFFFFFFu, ps, off);
            pd += __shfl_down_sync(0xFFFFFFFFu, pd, off);
        }
        if (row < valid) {
            if (lane == 0) { d_ssrc[base + row] = ps; d_sdst[base + row] = pd; }
            __half2 h01 = __floats2half2_rn(v.x, v.y);
            __half2 h23 = __floats2half2_rn(v.z, v.w);
            uint2 u;
            u.x = *(unsigned*)&h01;
            u.y = *(unsigned*)&h23;
            d_zh[(size_t)(base + row) * 32 + lane] = u;
        }
    }
}

// ---------------- CSR build --------------------------------------------------
__global__ void hist_kernel(const int* __restrict__ dst) {
    int i = blockIdx.x * blockDim.x + threadIdx.x;
    if (i >= N_EDGES) return;
    atomicAdd(&d_deg[__ldg(dst + i)], 1);
}

__global__ void chunksum_kernel() {
    __shared__ int sh[8];
    int idx = blockIdx.x * CHUNK + threadIdx.x;
    int v = (idx < N_NODES) ? d_deg[idx] : 0;
#pragma unroll
    for (int off = 16; off > 0; off >>= 1) v += __shfl_xor_sync(0xFFFFFFFFu, v, off);
    if ((threadIdx.x & 31) == 0) sh[threadIdx.x >> 5] = v;
    __syncthreads();
    if (threadIdx.x < 8) {
        int s = sh[threadIdx.x];
#pragma unroll
        for (int off = 4; off > 0; off >>= 1) s += __shfl_xor_sync(0xFFu, s, off);
        if (threadIdx.x == 0) d_chunksum[blockIdx.x] = s;
    }
}

__global__ void chunkscan_kernel() {
    __shared__ int sh[256];
    int t = threadIdx.x;
    int v = (t < NCHUNK) ? d_chunksum[t] : 0;
    sh[t] = v;
    __syncthreads();
#pragma unroll
    for (int off = 1; off < 256; off <<= 1) {
        int u = (t >= off) ? sh[t - off] : 0;
        __syncthreads();
        sh[t] += u;
        __syncthreads();
    }
    if (t < NCHUNK) d_chunkoff[t] = sh[t] - v;
    if (t == 0) d_rowstart[N_NODES] = N_EDGES;
}

__global__ void rowstart_kernel() {
    __shared__ int warp_sums[8];
    int t = threadIdx.x;
    int idx = blockIdx.x * CHUNK + t;
    int v = (idx < N_NODES) ? d_deg[idx] : 0;

    int incl = v;
#pragma unroll
    for (int off = 1; off < 32; off <<= 1) {
        int u = __shfl_up_sync(0xFFFFFFFFu, incl, off);
        if ((t & 31) >= off) incl += u;
    }
    if ((t & 31) == 31) warp_sums[t >> 5] = incl;
    __syncthreads();
    if (t < 8) {
        int s = warp_sums[t];
        int si = s;
#pragma unroll
        for (int off = 1; off < 8; off <<= 1) {
            int u = __shfl_up_sync(0xFFu, si, off);
            if (t >= off) si += u;
        }
        warp_sums[t] = si - s;
    }
    __syncthreads();
    int excl = incl - v + warp_sums[t >> 5];
    if (idx < N_NODES) {
        int rs = d_chunkoff[blockIdx.x] + excl;
        d_rowstart[idx] = rs;
        d_cursor[idx]   = rs;
    }
}

__global__ void fill_kernel(const int* __restrict__ src, const int* __restrict__ dst,
                            const float* __restrict__ sigma) {
    int i = blockIdx.x * blockDim.x + threadIdx.x;
    if (i >= N_EDGES) return;
    int d = __ldg(dst + i);
    int pos = atomicAdd(&d_cursor[d], 1);
    d_ecsr[pos] = make_int2(__ldg(src + i), __float_as_int(__ldg(sigma + i)));
}

// ---------------- fused per-node softmax + aggregation + BN stats -----------
// grid covers exactly N_NODES warps (50000 = 6250 blocks x 8 warps)
__global__ void node_kernel(const float* __restrict__ attn_b) {
    __shared__ float ssum[DIM];
    __shared__ float ssq[DIM];
    const int t = threadIdx.x;
    if (t < DIM) { ssum[t] = 0.f; ssq[t] = 0.f; }
    __syncthreads();

    const int node = (blockIdx.x * blockDim.x + t) >> 5;
    const int lane = t & 31;

    const int start = d_rowstart[node];
    const int end   = d_rowstart[node + 1];
    const float sd = d_sdst[node];
    const float b  = __ldg(attn_b);

    float sum_ex = 0.f, sum_sg = 0.f;
    for (int j = start + lane; j < end; j += 32) {
        int2 pr = d_ecsr[j];
        float a = d_ssrc[pr.x] + sd + b;
        float e = (a > 0.f) ? a : 0.01f * a;
        sum_ex += __expf(e);
        sum_sg += __int_as_float(pr.y);
    }
#pragma unroll
    for (int off = 16; off > 0; off >>= 1) {
        sum_ex += __shfl_xor_sync(0xFFFFFFFFu, sum_ex, off);
        sum_sg += __shfl_xor_sync(0xFFFFFFFFu, sum_sg, off);
    }
    const float inv = (end > start) ? 1.0f / (sum_ex * (sum_sg + EPS_BETA)) : 0.f;

    float4 acc = make_float4(0.f, 0.f, 0.f, 0.f);
    for (int j = start; j < end; j++) {
        int2  pr = d_ecsr[j];                      // uniform -> broadcast
        float a = d_ssrc[pr.x] + sd + b;
        float e = (a > 0.f) ? a : 0.01f * a;
        float wt = __expf(e) * __int_as_float(pr.y);
        uint2 zz = __ldg(reinterpret_cast<const uint2*>(d_zh) + (size_t)pr.x * 32 + lane);
        float2 f01 = __half22float2(*(__half2*)&zz.x);
        float2 f23 = __half22float2(*(__half2*)&zz.y);
        acc.x = fmaf(wt, f01.x, acc.x);
        acc.y = fmaf(wt, f01.y, acc.y);
        acc.z = fmaf(wt, f23.x, acc.z);
        acc.w = fmaf(wt, f23.y, acc.w);
    }
    acc.x *= inv; acc.y *= inv; acc.z *= inv; acc.w *= inv;
    *(reinterpret_cast<float4*>(d_hnew + (size_t)node * DIM) + lane) = acc;

    // block-local BN stats
    atomicAdd(&ssum[4 * lane + 0], acc.x);
    atomicAdd(&ssum[4 * lane + 1], acc.y);
    atomicAdd(&ssum[4 * lane + 2], acc.z);
    atomicAdd(&ssum[4 * lane + 3], acc.w);
    atomicAdd(&ssq[4 * lane + 0], acc.x * acc.x);
    atomicAdd(&ssq[4 * lane + 1], acc.y * acc.y);
    atomicAdd(&ssq[4 * lane + 2], acc.z * acc.z);
    atomicAdd(&ssq[4 * lane + 3], acc.w * acc.w);
    __syncthreads();

    const int wI = t >> 5;
    if (wI == 0) {
        float4 s = *(const float4*)&ssum[4 * lane];
        asm volatile("red.global.add.v4.f32 [%0], {%1, %2, %3, %4};"
                     :: "l"(d_colsum_f + 4 * lane), "f"(s.x), "f"(s.y), "f"(s.z), "f"(s.w)
                     : "memory");
    } else if (wI == 1) {
        float4 s = *(const float4*)&ssq[4 * lane];
        asm volatile("red.global.add.v4.f32 [%0], {%1, %2, %3, %4};"
                     :: "l"(d_colsq_f + 4 * lane), "f"(s.x), "f"(s.y), "f"(s.z), "f"(s.w)
                     : "memory");
    }
}

__global__ void finalize_kernel(const float* __restrict__ gamma,
                                const float* __restrict__ beta) {
    int c = threadIdx.x;
    if (c >= DIM) return;
    double mu  = (double)d_colsum_f[c] / (double)N_NODES;
    double var = (double)d_colsq_f[c] / (double)N_NODES - mu * mu;
    float rstd = rsqrtf((float)var + EPS_BN);
    float g = __ldg(gamma + c);
    float b = __ldg(beta + c);
    d_scale[c] = rstd * g;
    d_shift[c] = b - (float)mu * rstd * g;
}

// ---------------- normalize + ELU -------------------------------------------
__global__ void output_kernel(float* __restrict__ out) {
    int i = blockIdx.x * blockDim.x + threadIdx.x;
    if (i >= N_NODES * DIM) return;
    int c = i & (DIM - 1);
    float x = d_hnew[i] * d_scale[c] + d_shift[c];
    out[i] = (x > 0.f) ? x : expm1f(x);
}

// ---------------- launch -----------------------------------------------------
extern "C" void kernel_launch(void* const* d_in, const int* in_sizes, int n_in,
                              void* d_out, int out_size) {
    const float* h      = (const float*)d_in[0];
    const int*   src    = (const int*)  d_in[1];
    const int*   dst    = (const int*)  d_in[2];
    const float* sigma  = (const float*)d_in[3];
    const float* fc_w   = (const float*)d_in[4];
    const float* fc_b   = (const float*)d_in[5];
    const float* attn_w = (const float*)d_in[6];
    const float* attn_b = (const float*)d_in[7];
    const float* gamma  = (const float*)d_in[8];
    const float* beta   = (const float*)d_in[9];
    float* out = (float*)d_out;

    const int EB = (N_EDGES + 255) / 256;

    static cudaStream_t s_side = nullptr;
    static cudaEvent_t ev_fork = nullptr, ev_join = nullptr;
    if (s_side == nullptr) {
        cudaStreamCreateWithFlags(&s_side, cudaStreamNonBlocking);
        cudaEventCreateWithFlags(&ev_fork, cudaEventDisableTiming);
        cudaEventCreateWithFlags(&ev_join, cudaEventDisableTiming);
        cudaFuncSetAttribute(gemm_mma_kernel,
                             cudaFuncAttributeMaxDynamicSharedMemorySize, GEMM_SMEM);
    }

    init_kernel<<<64, 256>>>();
    cudaEventRecord(ev_fork, 0);
    cudaStreamWaitEvent(s_side, ev_fork, 0);

    // side stream: CSR build (independent of GEMM)
    hist_kernel<<<EB, 256, 0, s_side>>>(dst);
    chunksum_kernel<<<NCHUNK, 256, 0, s_side>>>();
    chunkscan_kernel<<<1, 256, 0, s_side>>>();
    rowstart_kernel<<<NCHUNK, 256, 0, s_side>>>();
    fill_kernel<<<EB, 256, 0, s_side>>>(src, dst, sigma);
    cudaEventRecord(ev_join, s_side);

    // main stream: weight split + GEMM
    wsplit_kernel<<<(DIM * DIM + 255) / 256, 256>>>(fc_w);
    gemm_mma_kernel<<<N_TILES, 256, GEMM_SMEM>>>(h, fc_b, attn_w);

    cudaStreamWaitEvent(0, ev_join, 0);
    node_kernel<<<(N_NODES + 7) / 8, 256>>>(attn_b);

    finalize_kernel<<<1, 128>>>(gamma, beta);
    output_kernel<<<(N_NODES * DIM + 1023) / 1024, 1024>>>(out);
}